// round 8
// baseline (speedup 1.0000x reference)
#include <cuda_runtime.h>
#include <cuda_fp16.h>
#include <cstdint>

#define NN 8192
#define EN 131072
#define CC 512
#define HH 8
#define DD 64
#define KR 256

// ---------------- scratch (__device__ globals, no allocation) ----------------
__device__ float g_Q[NN * CC];
__device__ float g_K[NN * CC];
__device__ float g_V[NN * CC];
__device__ float g_part[512 * 4096];     // 2M floats: pkv partials (128 x 16384)
__device__ float g_pK[HH * KR * DD];
__device__ float g_pV[HH * KR * DD];
__device__ float g_x[NN * CC];
__device__ __half g_Wh[4 * 512 * 512];
__device__ __half g_Wl[4 * 512 * 512];

// ===================== helpers =====================
__device__ __forceinline__ uint32_t smem_u32(const void* p) {
    uint32_t a;
    asm("{ .reg .u64 t; cvta.to.shared.u64 t, %1; cvt.u32.u64 %0, t; }" : "=r"(a) : "l"(p));
    return a;
}
#define SWZ64(b)  ((b) ^ (((b) >> 3) & 0x30))
#define SWZ128(b) ((b) ^ (((b) >> 3) & 0x70))

__device__ __forceinline__ void ldsm_x4(uint32_t* r, uint32_t a) {
    asm volatile("ldmatrix.sync.aligned.m8n8.x4.shared.b16 {%0,%1,%2,%3}, [%4];"
                 : "=r"(r[0]), "=r"(r[1]), "=r"(r[2]), "=r"(r[3]) : "r"(a));
}
__device__ __forceinline__ void ldsm_x4_trans(uint32_t* r, uint32_t a) {
    asm volatile("ldmatrix.sync.aligned.m8n8.x4.trans.shared.b16 {%0,%1,%2,%3}, [%4];"
                 : "=r"(r[0]), "=r"(r[1]), "=r"(r[2]), "=r"(r[3]) : "r"(a));
}
__device__ __forceinline__ void mma_f16(float* d, const uint32_t* a, const uint32_t* b) {
    asm volatile("mma.sync.aligned.m16n8k16.row.col.f32.f16.f16.f32 "
                 "{%0,%1,%2,%3}, {%4,%5,%6,%7}, {%8,%9}, {%0,%1,%2,%3};"
                 : "+f"(d[0]), "+f"(d[1]), "+f"(d[2]), "+f"(d[3])
                 : "r"(a[0]), "r"(a[1]), "r"(a[2]), "r"(a[3]), "r"(b[0]), "r"(b[1]));
}
__device__ __forceinline__ void cp_async16(uint32_t s, const void* g) {
    asm volatile("cp.async.cg.shared.global [%0], [%1], 16;" :: "r"(s), "l"(g) : "memory");
}
__device__ __forceinline__ void cp_commit() {
    asm volatile("cp.async.commit_group;" ::: "memory");
}
template<int N> __device__ __forceinline__ void cp_wait() {
    asm volatile("cp.async.wait_group %0;" :: "n"(N) : "memory");
}

// =====================================================================
// W -> fp16 hi/lo pre-conversion (4 weight matrices, 512x512 each)
// =====================================================================
__global__ void convert_w(const float* __restrict__ Wq, const float* __restrict__ Wk,
                          const float* __restrict__ Wv, const float* __restrict__ We)
{
    int i = blockIdx.x * 256 + threadIdx.x;
    int w = i >> 18;
    int off = i & 262143;
    const float* src = (w == 0) ? Wq : (w == 1) ? Wk : (w == 2) ? Wv : We;
    float f = src[off];
    __half h = __float2half_rn(f);
    g_Wh[i] = h;
    g_Wl[i] = __float2half_rn(f - __half2float(h));
}

// =====================================================================
// HMMA fp16 2-term GEMM: D[M,512] = X_h[M,512] @ (W_h + W_l)^T + bias
// mode 0: out = g_Q/g_K/g_V (blockIdx.y), bias only
// mode 1: out = out_edge, fused LayerNorm + residual(X)
// Block 64x512, BK=32, 8 warps (warp tile 64x64), double-buffered smem.
// MMA schedule: all-B-frags preloaded; hi-term block then lo-term block
// (same-acc reuse distance = 32 MMAs, hides HMMA D-latency).
// =====================================================================
__global__ __launch_bounds__(256)
void hmma_gemm(const float* __restrict__ X, int wbase, int mode,
               const float* __restrict__ b0, const float* __restrict__ b1,
               const float* __restrict__ b2,
               const float* __restrict__ gam, const float* __restrict__ bet,
               float* __restrict__ out_edge)
{
    extern __shared__ char dsm[];
    const uint32_t raw = smem_u32(dsm);
    const uint32_t sb = (raw + 1023) & ~1023u;
    char* sa = dsm + (sb - raw);

    const int tid  = threadIdx.x;
    const int lane = tid & 31;
    const int wid  = tid >> 5;
    const int y    = blockIdx.y;
    const int m0   = blockIdx.x * 64;

    const float* bias = (y == 0) ? b0 : (y == 1) ? b1 : b2;
    const int w = wbase + y;
    float* outp = mode ? out_edge : ((y == 0) ? g_Q : (y == 1) ? g_K : g_V);
    const __half* WH = g_Wh + ((size_t)w << 18);
    const __half* WL = g_Wl + ((size_t)w << 18);

    // stage: [A 4K][B_hi 32K][B_lo 32K] = 68K, x2
    const uint32_t ST = 69632;
    const uint32_t OFF_BH = 4096, OFF_BL = 36864;
    const uint32_t OFF_RED = 139264;
    float* redS  = (float*)(sa + OFF_RED);   // 8*64
    float* redQ  = redS + 512;
    float* muv   = redQ + 512;               // 64
    float* rsv   = muv + 64;                 // 64
    float* cbias = rsv + 64;                 // 512
    float* cg    = cbias + 512;              // 512
    float* cbt   = cg + 512;                 // 512

    for (int i = tid; i < 512; i += 256) {
        cbias[i] = bias[i];
        if (mode) { cg[i] = gam[i]; cbt[i] = bet[i]; }
    }

    float acc[4][8][4];
#pragma unroll
    for (int mf = 0; mf < 4; ++mf)
#pragma unroll
        for (int nf = 0; nf < 8; ++nf)
#pragma unroll
            for (int j = 0; j < 4; ++j) acc[mf][nf][j] = 0.f;

    // ---------- loaders ----------
    auto ldgA = [&](int it, float4* r) {
        const int k0 = it * 32;
#pragma unroll
        for (int h = 0; h < 2; ++h) {
            int i = tid + h * 256;           // float4 index, 512 total
            int row = i >> 3, kq = i & 7;
            r[h] = *(const float4*)(X + (size_t)(m0 + row) * 512 + k0 + kq * 4);
        }
    };
    auto stsA = [&](int it, const float4* r) {
        char* dst = sa + (size_t)(it & 1) * ST;
#pragma unroll
        for (int h = 0; h < 2; ++h) {
            int i = tid + h * 256;
            int row = i >> 3, kq = i & 7;
            __half2 h0 = __floats2half2_rn(r[h].x, r[h].y);
            __half2 h1 = __floats2half2_rn(r[h].z, r[h].w);
            uint32_t off = SWZ64((uint32_t)(row * 64 + kq * 8));
            *(uint2*)(dst + off) = make_uint2(*(uint32_t*)&h0, *(uint32_t*)&h1);
        }
    };
    auto loadB = [&](int it) {
        const int k0 = it * 32;
        const uint32_t dH = sb + (uint32_t)(it & 1) * ST + OFF_BH;
        const uint32_t dL = sb + (uint32_t)(it & 1) * ST + OFF_BL;
#pragma unroll
        for (int h = 0; h < 8; ++h) {
            int c = tid + h * 256;           // 0..2047 16B chunks
            int n = c >> 2, sub = c & 3;
            uint32_t off = SWZ64((uint32_t)(n * 64 + sub * 16));
            cp_async16(dH + off, WH + (size_t)n * 512 + k0 + sub * 8);
            cp_async16(dL + off, WL + (size_t)n * 512 + k0 + sub * 8);
        }
        cp_commit();
    };

    float4 ra[2], rn[2];
    ldgA(0, ra);
    loadB(0);

    for (int it = 0; it < 16; ++it) {
        stsA(it, ra);                        // write buf(it&1)
        if (it < 15) {
            ldgA(it + 1, rn);                // LDGs fly during compute
            loadB(it + 1);
        }
        if (it < 15) cp_wait<1>(); else cp_wait<0>();
        __syncthreads();                     // stage it visible

        const uint32_t stg = sb + (uint32_t)(it & 1) * ST;
#pragma unroll
        for (int kk = 0; kk < 2; ++kk) {
            // ---- preload A frags (hi only) ----
            uint32_t ah[4][4];
#pragma unroll
            for (int mf = 0; mf < 4; ++mf) {
                int m = mf * 16 + (lane & 7) + ((lane >> 3) & 1) * 8;
                int ks = kk * 2 + (lane >> 4);
                ldsm_x4(ah[mf], stg + SWZ64((uint32_t)(m * 64 + ks * 16)));
            }
            // ---- preload ALL B frags via x4 (2 nf per ldsm) ----
            uint32_t bh[8][2], bl[8][2];
#pragma unroll
            for (int nfp = 0; nfp < 4; ++nfp) {
                int n  = wid * 64 + nfp * 16 + ((lane >> 4) & 1) * 8 + (lane & 7);
                int ks = kk * 2 + ((lane >> 3) & 1);
                uint32_t off = SWZ64((uint32_t)(n * 64 + ks * 16));
                uint32_t r[4];
                ldsm_x4(r, stg + OFF_BH + off);
                bh[nfp * 2][0] = r[0]; bh[nfp * 2][1] = r[1];
                bh[nfp * 2 + 1][0] = r[2]; bh[nfp * 2 + 1][1] = r[3];
                ldsm_x4(r, stg + OFF_BL + off);
                bl[nfp * 2][0] = r[0]; bl[nfp * 2][1] = r[1];
                bl[nfp * 2 + 1][0] = r[2]; bl[nfp * 2 + 1][1] = r[3];
            }
            // ---- hi term: 32 MMAs, no same-acc reuse inside ----
#pragma unroll
            for (int nf = 0; nf < 8; ++nf)
#pragma unroll
                for (int mf = 0; mf < 4; ++mf)
                    mma_f16(acc[mf][nf], ah[mf], bh[nf]);
            // ---- lo term ----
#pragma unroll
            for (int nf = 0; nf < 8; ++nf)
#pragma unroll
                for (int mf = 0; mf < 4; ++mf)
                    mma_f16(acc[mf][nf], ah[mf], bl[nf]);
        }
        __syncthreads();                     // done reading buf(it&1)
        ra[0] = rn[0]; ra[1] = rn[1];
    }

    // ---- bias add ----
#pragma unroll
    for (int nf = 0; nf < 8; ++nf) {
        float c0 = cbias[wid * 64 + nf * 8 + 2 * (lane & 3)];
        float c1 = cbias[wid * 64 + nf * 8 + 2 * (lane & 3) + 1];
#pragma unroll
        for (int mf = 0; mf < 4; ++mf) {
            acc[mf][nf][0] += c0; acc[mf][nf][1] += c1;
            acc[mf][nf][2] += c0; acc[mf][nf][3] += c1;
        }
    }

    if (mode) {
        // ---- per-row stats ----
#pragma unroll
        for (int mf = 0; mf < 4; ++mf) {
#pragma unroll
            for (int h = 0; h < 2; ++h) {
                float s = 0.f, q = 0.f;
#pragma unroll
                for (int nf = 0; nf < 8; ++nf) {
#pragma unroll
                    for (int jj = 0; jj < 2; ++jj) {
                        float v = acc[mf][nf][h * 2 + jj];
                        s += v; q += v * v;
                    }
                }
                s += __shfl_xor_sync(0xffffffffu, s, 1);
                s += __shfl_xor_sync(0xffffffffu, s, 2);
                q += __shfl_xor_sync(0xffffffffu, q, 1);
                q += __shfl_xor_sync(0xffffffffu, q, 2);
                if ((lane & 3) == 0) {
                    int row = mf * 16 + h * 8 + (lane >> 2);
                    redS[wid * 64 + row] = s;
                    redQ[wid * 64 + row] = q;
                }
            }
        }
        __syncthreads();
        if (tid < 64) {
            float s = 0.f, q = 0.f;
#pragma unroll
            for (int w8 = 0; w8 < 8; ++w8) { s += redS[w8 * 64 + tid]; q += redQ[w8 * 64 + tid]; }
            float mu = s * (1.f / 512.f);
            float var = q * (1.f / 512.f) - mu * mu;
            muv[tid] = mu;
            rsv[tid] = rsqrtf(var + 1e-5f);
        }
        __syncthreads();
    }

    // ---- frag store into per-warp smem tile ----
    float* tile = (float*)(sa + (size_t)wid * 16384);
#pragma unroll
    for (int mf = 0; mf < 4; ++mf) {
#pragma unroll
        for (int h = 0; h < 2; ++h) {
            int row = mf * 16 + h * 8 + (lane >> 2);
            float mu = 0.f, rs = 1.f;
            if (mode) { mu = muv[row]; rs = rsv[row]; }
#pragma unroll
            for (int nf = 0; nf < 8; ++nf) {
                int colw = nf * 8 + 2 * (lane & 3);
                float v0 = acc[mf][nf][h * 2 + 0];
                float v1 = acc[mf][nf][h * 2 + 1];
                if (mode) { v0 = (v0 - mu) * rs; v1 = (v1 - mu) * rs; }
                tile[row * 64 + colw]     = v0;
                tile[row * 64 + colw + 1] = v1;
            }
        }
    }
    __syncthreads();

    // ---- coalesced global store ----
#pragma unroll
    for (int i = 0; i < 32; ++i) {
        int idx = i * 256 + tid;
        int row = idx >> 7;
        int col = (idx & 127) * 4;
        const float* src = (const float*)(sa + (size_t)(col >> 6) * 16384) + row * 64 + (col & 63);
        float4 v = *(const float4*)src;
        size_t gi = (size_t)(m0 + row) * 512 + col;
        if (mode) {
            float4 g4 = *(const float4*)(cg + col);
            float4 b4 = *(const float4*)(cbt + col);
            float4 r4 = *(const float4*)(X + gi);
            v.x = v.x * g4.x + b4.x + r4.x;
            v.y = v.y * g4.y + b4.y + r4.y;
            v.z = v.z * g4.z + b4.z + r4.z;
            v.w = v.w * g4.w + b4.w + r4.w;
        }
        *(float4*)(outp + gi) = v;
    }
}

// =====================================================================
// pkv HMMA: partial[hw,seg] = P_h[h,:,seg] @ (KV_h + KV_l)[seg, h*64:+64]
// grid (seg=8, hw=16); block 256 thr, 8 warps: warp grid 4(M)x2(N),
// warp tile 64x32, M=256, N=64, inner 1024, BK=32.
// =====================================================================
__global__ __launch_bounds__(256)
void pkv_hmma(const float* __restrict__ Ep, const float* __restrict__ Fp)
{
    extern __shared__ char dsm[];
    const uint32_t raw = smem_u32(dsm);
    const uint32_t sb = (raw + 1023) & ~1023u;
    char* sa = dsm + (sb - raw);

    const int seg = blockIdx.x;       // 0..7
    const int hw  = blockIdx.y;       // 0..15
    const int h   = hw >> 1, w = hw & 1;
    const float* P  = w ? Fp : Ep;
    const float* KV = w ? g_V : g_K;
    const int n0base = seg * 1024;

    const int tid  = threadIdx.x;
    const int lane = tid & 31;
    const int wid  = tid >> 5;
    const int wm   = wid & 3;         // M quadrant (64 rows)
    const int wn   = wid >> 2;        // N half (32 cols)

    // stage: [A 16K][B_hi 4K][B_lo 4K] = 24K x2
    const uint32_t ST = 24576;
    const uint32_t OFF_BH = 16384, OFF_BL = 20480;

    float acc[4][4][4];
#pragma unroll
    for (int mf = 0; mf < 4; ++mf)
#pragma unroll
        for (int nf = 0; nf < 4; ++nf)
#pragma unroll
            for (int j = 0; j < 4; ++j) acc[mf][nf][j] = 0.f;

    auto ldg = [&](int c, float4* a, float4* b) {
        const int col = n0base + c * 32;
#pragma unroll
        for (int t = 0; t < 8; ++t) {
            int f = tid + t * 256;           // 2048 float4s = 256x32
            int row = f >> 3, kq = f & 7;
            a[t] = *(const float4*)(P + (size_t)(h * 256 + row) * 8192 + col + kq * 4);
        }
#pragma unroll
        for (int t = 0; t < 2; ++t) {
            int f = tid + t * 256;           // 512 float4s = 32x64
            int row = f >> 4, dq = f & 15;
            b[t] = *(const float4*)(KV + (size_t)(col + row) * 512 + h * 64 + dq * 4);
        }
    };
    auto sts = [&](int c, const float4* a, const float4* b) {
        char* dst = sa + (size_t)(c & 1) * ST;
#pragma unroll
        for (int t = 0; t < 8; ++t) {
            int f = tid + t * 256;
            int row = f >> 3, kq = f & 7;
            __half2 h0 = __floats2half2_rn(a[t].x, a[t].y);
            __half2 h1 = __floats2half2_rn(a[t].z, a[t].w);
            uint32_t off = SWZ64((uint32_t)(row * 64 + kq * 8));
            *(uint2*)(dst + off) = make_uint2(*(uint32_t*)&h0, *(uint32_t*)&h1);
        }
#pragma unroll
        for (int t = 0; t < 2; ++t) {
            int f = tid + t * 256;
            int row = f >> 4, dq = f & 15;
            float4 v = b[t];
            __half2 h0 = __floats2half2_rn(v.x, v.y);
            __half2 h1 = __floats2half2_rn(v.z, v.w);
            __half2 l0 = __floats2half2_rn(v.x - __half2float(__low2half(h0)),
                                           v.y - __half2float(__high2half(h0)));
            __half2 l1 = __floats2half2_rn(v.z - __half2float(__low2half(h1)),
                                           v.w - __half2float(__high2half(h1)));
            uint32_t off = SWZ128((uint32_t)(row * 128 + dq * 8));
            *(uint2*)(dst + OFF_BH + off) = make_uint2(*(uint32_t*)&h0, *(uint32_t*)&h1);
            *(uint2*)(dst + OFF_BL + off) = make_uint2(*(uint32_t*)&l0, *(uint32_t*)&l1);
        }
    };

    float4 ra[8], rb[2], na[8], nb[2];
    ldg(0, ra, rb);

    for (int c = 0; c < 32; ++c) {
        sts(c, ra, rb);
        if (c < 31) ldg(c + 1, na, nb);
        __syncthreads();

        const uint32_t stg = sb + (uint32_t)(c & 1) * ST;
#pragma unroll
        for (int kk = 0; kk < 2; ++kk) {
            uint32_t ah[4][4];
#pragma unroll
            for (int mf = 0; mf < 4; ++mf) {
                int m = wm * 64 + mf * 16 + (lane & 7) + ((lane >> 3) & 1) * 8;
                int ks = kk * 2 + (lane >> 4);
                ldsm_x4(ah[mf], stg + SWZ64((uint32_t)(m * 64 + ks * 16)));
            }
            // preload all B frags (x4 trans: 2 nf per ldsm)
            uint32_t bh[4][2], bl[4][2];
#pragma unroll
            for (int nfp = 0; nfp < 2; ++nfp) {
                int k = kk * 16 + (lane & 15);
                int n = wn * 32 + nfp * 16 + ((lane >> 4) & 1) * 8;
                uint32_t off = SWZ128((uint32_t)(k * 128 + n * 2));
                uint32_t r[4];
                ldsm_x4_trans(r, stg + OFF_BH + off);
                bh[nfp * 2][0] = r[0]; bh[nfp * 2][1] = r[1];
                bh[nfp * 2 + 1][0] = r[2]; bh[nfp * 2 + 1][1] = r[3];
                ldsm_x4_trans(r, stg + OFF_BL + off);
                bl[nfp * 2][0] = r[0]; bl[nfp * 2][1] = r[1];
                bl[nfp * 2 + 1][0] = r[2]; bl[nfp * 2 + 1][1] = r[3];
            }
#pragma unroll
            for (int nf = 0; nf < 4; ++nf)
#pragma unroll
                for (int mf = 0; mf < 4; ++mf)
                    mma_f16(acc[mf][nf], ah[mf], bh[nf]);
#pragma unroll
            for (int nf = 0; nf < 4; ++nf)
#pragma unroll
                for (int mf = 0; mf < 4; ++mf)
                    mma_f16(acc[mf][nf], ah[mf], bl[nf]);
        }
        __syncthreads();
#pragma unroll
        for (int t = 0; t < 8; ++t) ra[t] = na[t];
        rb[0] = nb[0]; rb[1] = nb[1];
    }

    // ---- store partials ----
    float* dst = g_part + (size_t)(hw * 8 + seg) * 16384;
#pragma unroll
    for (int mf = 0; mf < 4; ++mf) {
#pragma unroll
        for (int nf = 0; nf < 4; ++nf) {
            int m = wm * 64 + mf * 16 + (lane >> 2);
            int n = wn * 32 + nf * 8 + (lane & 3) * 2;
            *(float2*)(dst + m * 64 + n)       = make_float2(acc[mf][nf][0], acc[mf][nf][1]);
            *(float2*)(dst + (m + 8) * 64 + n) = make_float2(acc[mf][nf][2], acc[mf][nf][3]);
        }
    }
}

__global__ void pkv_reduce()
{
    int o = blockIdx.x * 256 + threadIdx.x;   // 0..262143
    int d  = o & 63;
    int k  = (o >> 6) & 255;
    int h  = (o >> 14) & 7;
    int w  = o >> 17;
    int hw = h * 2 + w;
    float s = 0.f;
#pragma unroll
    for (int sp = 0; sp < 8; sp++)
        s += g_part[(size_t)(hw * 8 + sp) * 16384 + k * 64 + d];
    float* dst = w ? g_pV : g_pK;
    dst[((h << 8) + k) * 64 + d] = s;
}

// =====================================================================
// Fused attention (fp32), 512 threads: scores -> softmax -> out
// =====================================================================
__global__ __launch_bounds__(512)
void attn_kernel()
{
    extern __shared__ float sm[];
    float* pKs = sm;                       // 256*65
    float* pVs = pKs + 256 * 65;           // 256*65
    float* Qs  = pVs + 256 * 65;           // 64*65
    float* Ss  = Qs  + 64 * 65;            // 64*257

    const int h   = blockIdx.y;
    const int n0  = blockIdx.x * 64;
    const int tid = threadIdx.x;

#pragma unroll
    for (int i = 0; i < 8; i++) {
        int f = tid + i * 512;
        int k = f >> 4, dq = f & 15;
        float4 v = *(const float4*)(g_pK + (size_t)(h * 256 + k) * 64 + dq * 4);
        float* dst = &pKs[k * 65 + dq * 4];
        dst[0] = v.x; dst[1] = v.y; dst[2] = v.z; dst[3] = v.w;
        float4 u = *(const float4*)(g_pV + (size_t)(h * 256 + k) * 64 + dq * 4);
        float* dst2 = &pVs[k * 65 + dq * 4];
        dst2[0] = u.x; dst2[1] = u.y; dst2[2] = u.z; dst2[3] = u.w;
    }
#pragma unroll
    for (int i = 0; i < 2; i++) {
        int f = tid + i * 512;
        int m = f >> 4, dq = f & 15;
        float4 v = *(const float4*)(g_Q + (size_t)(n0 + m) * 512 + h * 64 + dq * 4);
        float* dst = &Qs[m * 65 + dq * 4];
        dst[0] = v.x; dst[1] = v.y; dst[2] = v.z; dst[3] = v.w;
    }
    __syncthreads();

    const int tm = tid >> 6;   // 0..7
    const int tj = tid & 63;   // 0..63
    {
        float acc[8][4];
#pragma unroll
        for (int r = 0; r < 8; r++)
#pragma unroll
            for (int c = 0; c < 4; c++) acc[r][c] = 0.f;
#pragma unroll 4
        for (int d = 0; d < 64; d++) {
            float a[8], b[4];
#pragma unroll
            for (int r = 0; r < 8; r++) a[r] = Qs[(tm + 8 * r) * 65 + d];
#pragma unroll
            for (int c = 0; c < 4; c++) b[c] = pKs[(tj + 64 * c) * 65 + d];
#pragma unroll
            for (int r = 0; r < 8; r++)
#pragma unroll
                for (int c = 0; c < 4; c++)
                    acc[r][c] = fmaf(a[r], b[c], acc[r][c]);
        }
#pragma unroll
        for (int r = 0; r < 8; r++)
#pragma unroll
            for (int c = 0; c < 4; c++)
                Ss[(tm + 8 * r) * 257 + tj + 64 * c] = acc[r][c] * 0.125f;
    }
    __syncthreads();

    // ---- softmax: 16 warps x 4 rows ----
    {
        const int wp = tid >> 5, ln = tid & 31;
#pragma unroll
        for (int rr = 0; rr < 4; rr++) {
            int m = wp * 4 + rr;
            float v[8];
            float mx = -1e30f;
#pragma unroll
            for (int i = 0; i < 8; i++) { v[i] = Ss[m * 257 + ln + 32 * i]; mx = fmaxf(mx, v[i]); }
#pragma unroll
            for (int o = 16; o > 0; o >>= 1) mx = fmaxf(mx, __shfl_xor_sync(0xffffffffu, mx, o));
            float sum = 0.f;
#pragma unroll
            for (int i = 0; i < 8; i++) { v[i] = __expf(v[i] - mx); sum += v[i]; }
#pragma unroll
            for (int o = 16; o > 0; o >>= 1) sum += __shfl_xor_sync(0xffffffffu, sum, o);
            float inv = 1.f / sum;
#pragma unroll
            for (int i = 0; i < 8; i++) Ss[m * 257 + ln + 32 * i] = v[i] * inv;
        }
    }
    __syncthreads();

    // ---- out: O[m, d] = sum_j attn[m,j] * pV[j,d] ----
    {
        float o2[8];
#pragma unroll
        for (int r = 0; r < 8; r++) o2[r] = 0.f;
#pragma unroll 4
        for (int j = 0; j < 256; j++) {
            float b0 = pVs[j * 65 + tj];
#pragma unroll
            for (int r = 0; r < 8; r++)
                o2[r] = fmaf(Ss[(tm + 8 * r) * 257 + j], b0, o2[r]);
        }
#pragma unroll
        for (int r = 0; r < 8; r++)
            g_x[(size_t)(n0 + tm + 8 * r) * 512 + h * 64 + tj] = o2[r];
    }
}

// =====================================================================
// node LayerNorm + residual
// =====================================================================
__global__ __launch_bounds__(128)
void node_ln_kernel(const float* __restrict__ nf,
                    const float* __restrict__ gam, const float* __restrict__ bet,
                    float* __restrict__ out)
{
    const int row = blockIdx.x;
    const int tid = threadIdx.x;
    const float* xr = g_x + (size_t)row * 512;

    float v[4];
    float s = 0.f, q = 0.f;
#pragma unroll
    for (int i = 0; i < 4; i++) {
        v[i] = xr[tid + 128 * i];
        s += v[i];
        q += v[i] * v[i];
    }
#pragma unroll
    for (int o = 16; o > 0; o >>= 1) {
        s += __shfl_xor_sync(0xffffffffu, s, o);
        q += __shfl_xor_sync(0xffffffffu, q, o);
    }
    __shared__ float rs[4], rq[4], mv[2];
    const int wp = tid >> 5, ln = tid & 31;
    if (ln == 0) { rs[wp] = s; rq[wp] = q; }
    __syncthreads();
    if (tid == 0) {
        float S = rs[0] + rs[1] + rs[2] + rs[3];
        float Qq = rq[0] + rq[1] + rq[2] + rq[3];
        float mu  = S * (1.f / 512.f);
        float var = Qq * (1.f / 512.f) - mu * mu;
        mv[0] = mu;
        mv[1] = rsqrtf(var + 1e-5f);
    }
    __syncthreads();
    const float mu = mv[0], rstd = mv[1];
#pragma unroll
    for (int i = 0; i < 4; i++) {
        int c = tid + 128 * i;
        out[(size_t)row * 512 + c] =
            (v[i] - mu) * rstd * gam[c] + bet[c] + nf[(size_t)row * 512 + c];
    }
}

// =====================================================================
// launch
// =====================================================================
extern "C" void kernel_launch(void* const* d_in, const int* in_sizes, int n_in,
                              void* d_out, int out_size)
{
    const float* node  = (const float*)d_in[0];
    const float* edge  = (const float*)d_in[1];
    const float* Wq    = (const float*)d_in[2];
    const float* bq    = (const float*)d_in[3];
    const float* Wk    = (const float*)d_in[4];
    const float* bk    = (const float*)d_in[5];
    const float* Wv    = (const float*)d_in[6];
    const float* bv    = (const float*)d_in[7];
    const float* We    = (const float*)d_in[8];
    const float* be    = (const float*)d_in[9];
    const float* Ep    = (const float*)d_in[10];
    const float* Fp    = (const float*)d_in[11];
    const float* ln_ng = (const float*)d_in[12];
    const float* ln_nb = (const float*)d_in[13];
    const float* ln_eg = (const float*)d_in[14];
    const float* ln_eb = (const float*)d_in[15];
    float* out = (float*)d_out;

    const int attn_smem = (2 * 256 * 65 + 64 * 65 + 64 * 257) * 4;  // 215,552 B
    cudaFuncSetAttribute(attn_kernel, cudaFuncAttributeMaxDynamicSharedMemorySize, attn_smem);
    const int gemm_smem = 150016 + 1024;
    cudaFuncSetAttribute(hmma_gemm, cudaFuncAttributeMaxDynamicSharedMemorySize, gemm_smem);
    const int pkv_smem = 49152 + 1024;
    cudaFuncSetAttribute(pkv_hmma, cudaFuncAttributeMaxDynamicSharedMemorySize, pkv_smem);

    // 0) W -> fp16 hi/lo
    convert_w<<<4096, 256>>>(Wq, Wk, Wv, We);
    // 1) QKV projections
    hmma_gemm<<<dim3(128, 3), 256, gemm_smem>>>(node, 0, 0, bq, bk, bv,
                                                nullptr, nullptr, nullptr);
    // 2) low-rank K/V projections (HMMA split-inner + reduce)
    pkv_hmma<<<dim3(8, 16), 256, pkv_smem>>>(Ep, Fp);
    pkv_reduce<<<1024, 256>>>();
    // 3) fused attention -> g_x
    attn_kernel<<<dim3(128, 8), 512, attn_smem>>>();
    // 4) node LN + residual -> out[0 : N*C)
    node_ln_kernel<<<8192, 128>>>(node, ln_ng, ln_nb, out);
    // 5) edge GEMM + bias + LN + residual -> out[N*C : )
    hmma_gemm<<<dim3(2048, 1), 256, gemm_smem>>>(edge, 3, 1, be, be, be,
                                                 ln_eg, ln_eb, out + (size_t)NN * CC);
}

// round 12
// speedup vs baseline: 1.0018x; 1.0018x over previous
#include <cuda_runtime.h>
#include <cuda_fp16.h>
#include <cstdint>

#define NN 8192
#define EN 131072
#define CC 512
#define HH 8
#define DD 64
#define KR 256

// ---------------- scratch (__device__ globals, no allocation) ----------------
__device__ float g_Q[NN * CC];
__device__ float g_K[NN * CC];
__device__ float g_V[NN * CC];
__device__ float g_part[512 * 4096];     // 2M floats: pkv partials (128 x 16384)
__device__ float g_pK[HH * KR * DD];
__device__ float g_pV[HH * KR * DD];
__device__ float g_x[NN * CC];
__device__ __half g_Wh[4 * 512 * 512];
__device__ __half g_Wl[4 * 512 * 512];

// ===================== helpers =====================
__device__ __forceinline__ uint32_t smem_u32(const void* p) {
    uint32_t a;
    asm("{ .reg .u64 t; cvta.to.shared.u64 t, %1; cvt.u32.u64 %0, t; }" : "=r"(a) : "l"(p));
    return a;
}
#define SWZ64(b)  ((b) ^ (((b) >> 3) & 0x30))
#define SWZ128(b) ((b) ^ (((b) >> 3) & 0x70))

__device__ __forceinline__ void ldsm_x4(uint32_t* r, uint32_t a) {
    asm volatile("ldmatrix.sync.aligned.m8n8.x4.shared.b16 {%0,%1,%2,%3}, [%4];"
                 : "=r"(r[0]), "=r"(r[1]), "=r"(r[2]), "=r"(r[3]) : "r"(a));
}
__device__ __forceinline__ void ldsm_x4_trans(uint32_t* r, uint32_t a) {
    asm volatile("ldmatrix.sync.aligned.m8n8.x4.trans.shared.b16 {%0,%1,%2,%3}, [%4];"
                 : "=r"(r[0]), "=r"(r[1]), "=r"(r[2]), "=r"(r[3]) : "r"(a));
}
__device__ __forceinline__ void mma_f16(float* d, const uint32_t* a, const uint32_t* b) {
    asm volatile("mma.sync.aligned.m16n8k16.row.col.f32.f16.f16.f32 "
                 "{%0,%1,%2,%3}, {%4,%5,%6,%7}, {%8,%9}, {%0,%1,%2,%3};"
                 : "+f"(d[0]), "+f"(d[1]), "+f"(d[2]), "+f"(d[3])
                 : "r"(a[0]), "r"(a[1]), "r"(a[2]), "r"(a[3]), "r"(b[0]), "r"(b[1]));
}
__device__ __forceinline__ void cp_async16(uint32_t s, const void* g) {
    asm volatile("cp.async.cg.shared.global [%0], [%1], 16;" :: "r"(s), "l"(g) : "memory");
}
__device__ __forceinline__ void cp_commit() {
    asm volatile("cp.async.commit_group;" ::: "memory");
}
template<int N> __device__ __forceinline__ void cp_wait() {
    asm volatile("cp.async.wait_group %0;" :: "n"(N) : "memory");
}

// =====================================================================
// W -> fp16 hi/lo pre-conversion (4 weight matrices, 512x512 each)
// =====================================================================
__global__ void convert_w(const float* __restrict__ Wq, const float* __restrict__ Wk,
                          const float* __restrict__ Wv, const float* __restrict__ We)
{
    int i = blockIdx.x * 256 + threadIdx.x;
    int w = i >> 18;
    int off = i & 262143;
    const float* src = (w == 0) ? Wq : (w == 1) ? Wk : (w == 2) ? Wv : We;
    float f = src[off];
    __half h = __float2half_rn(f);
    g_Wh[i] = h;
    g_Wl[i] = __float2half_rn(f - __half2float(h));
}

// =====================================================================
// HMMA fp16 2-term GEMM: D[M,512] = X_h[M,512] @ (W_h + W_l)^T + bias
// mode 0: out = g_Q/g_K/g_V (blockIdx.y), bias only
// mode 1: out = out_edge, fused LayerNorm + residual(X)
// Block 64x512, BK=32, 8 warps (warp tile 64x64), double-buffered smem.
// MMA schedule: all-B-frags preloaded; hi-term block then lo-term block
// (same-acc reuse distance = 32 MMAs, hides HMMA D-latency).
// =====================================================================
__global__ __launch_bounds__(256)
void hmma_gemm(const float* __restrict__ X, int wbase, int mode,
               const float* __restrict__ b0, const float* __restrict__ b1,
               const float* __restrict__ b2,
               const float* __restrict__ gam, const float* __restrict__ bet,
               float* __restrict__ out_edge)
{
    extern __shared__ char dsm[];
    const uint32_t raw = smem_u32(dsm);
    const uint32_t sb = (raw + 1023) & ~1023u;
    char* sa = dsm + (sb - raw);

    const int tid  = threadIdx.x;
    const int lane = tid & 31;
    const int wid  = tid >> 5;
    const int y    = blockIdx.y;
    const int m0   = blockIdx.x * 64;

    const float* bias = (y == 0) ? b0 : (y == 1) ? b1 : b2;
    const int w = wbase + y;
    float* outp = mode ? out_edge : ((y == 0) ? g_Q : (y == 1) ? g_K : g_V);
    const __half* WH = g_Wh + ((size_t)w << 18);
    const __half* WL = g_Wl + ((size_t)w << 18);

    // stage: [A 4K][B_hi 32K][B_lo 32K] = 68K, x2
    const uint32_t ST = 69632;
    const uint32_t OFF_BH = 4096, OFF_BL = 36864;
    const uint32_t OFF_RED = 139264;
    float* redS  = (float*)(sa + OFF_RED);   // 8*64
    float* redQ  = redS + 512;
    float* muv   = redQ + 512;               // 64
    float* rsv   = muv + 64;                 // 64
    float* cbias = rsv + 64;                 // 512
    float* cg    = cbias + 512;              // 512
    float* cbt   = cg + 512;                 // 512

    for (int i = tid; i < 512; i += 256) {
        cbias[i] = bias[i];
        if (mode) { cg[i] = gam[i]; cbt[i] = bet[i]; }
    }

    float acc[4][8][4];
#pragma unroll
    for (int mf = 0; mf < 4; ++mf)
#pragma unroll
        for (int nf = 0; nf < 8; ++nf)
#pragma unroll
            for (int j = 0; j < 4; ++j) acc[mf][nf][j] = 0.f;

    // ---------- loaders ----------
    auto ldgA = [&](int it, float4* r) {
        const int k0 = it * 32;
#pragma unroll
        for (int h = 0; h < 2; ++h) {
            int i = tid + h * 256;           // float4 index, 512 total
            int row = i >> 3, kq = i & 7;
            r[h] = *(const float4*)(X + (size_t)(m0 + row) * 512 + k0 + kq * 4);
        }
    };
    auto stsA = [&](int it, const float4* r) {
        char* dst = sa + (size_t)(it & 1) * ST;
#pragma unroll
        for (int h = 0; h < 2; ++h) {
            int i = tid + h * 256;
            int row = i >> 3, kq = i & 7;
            __half2 h0 = __floats2half2_rn(r[h].x, r[h].y);
            __half2 h1 = __floats2half2_rn(r[h].z, r[h].w);
            uint32_t off = SWZ64((uint32_t)(row * 64 + kq * 8));
            *(uint2*)(dst + off) = make_uint2(*(uint32_t*)&h0, *(uint32_t*)&h1);
        }
    };
    auto loadB = [&](int it) {
        const int k0 = it * 32;
        const uint32_t dH = sb + (uint32_t)(it & 1) * ST + OFF_BH;
        const uint32_t dL = sb + (uint32_t)(it & 1) * ST + OFF_BL;
#pragma unroll
        for (int h = 0; h < 8; ++h) {
            int c = tid + h * 256;           // 0..2047 16B chunks
            int n = c >> 2, sub = c & 3;
            uint32_t off = SWZ64((uint32_t)(n * 64 + sub * 16));
            cp_async16(dH + off, WH + (size_t)n * 512 + k0 + sub * 8);
            cp_async16(dL + off, WL + (size_t)n * 512 + k0 + sub * 8);
        }
        cp_commit();
    };

    float4 ra[2], rn[2];
    ldgA(0, ra);
    loadB(0);

    for (int it = 0; it < 16; ++it) {
        stsA(it, ra);                        // write buf(it&1)
        if (it < 15) {
            ldgA(it + 1, rn);                // LDGs fly during compute
            loadB(it + 1);
        }
        if (it < 15) cp_wait<1>(); else cp_wait<0>();
        __syncthreads();                     // stage it visible

        const uint32_t stg = sb + (uint32_t)(it & 1) * ST;
#pragma unroll
        for (int kk = 0; kk < 2; ++kk) {
            // ---- preload A frags (hi only) ----
            uint32_t ah[4][4];
#pragma unroll
            for (int mf = 0; mf < 4; ++mf) {
                int m = mf * 16 + (lane & 7) + ((lane >> 3) & 1) * 8;
                int ks = kk * 2 + (lane >> 4);
                ldsm_x4(ah[mf], stg + SWZ64((uint32_t)(m * 64 + ks * 16)));
            }
            // ---- preload ALL B frags via x4 (2 nf per ldsm) ----
            uint32_t bh[8][2], bl[8][2];
#pragma unroll
            for (int nfp = 0; nfp < 4; ++nfp) {
                int n  = wid * 64 + nfp * 16 + ((lane >> 4) & 1) * 8 + (lane & 7);
                int ks = kk * 2 + ((lane >> 3) & 1);
                uint32_t off = SWZ64((uint32_t)(n * 64 + ks * 16));
                uint32_t r[4];
                ldsm_x4(r, stg + OFF_BH + off);
                bh[nfp * 2][0] = r[0]; bh[nfp * 2][1] = r[1];
                bh[nfp * 2 + 1][0] = r[2]; bh[nfp * 2 + 1][1] = r[3];
                ldsm_x4(r, stg + OFF_BL + off);
                bl[nfp * 2][0] = r[0]; bl[nfp * 2][1] = r[1];
                bl[nfp * 2 + 1][0] = r[2]; bl[nfp * 2 + 1][1] = r[3];
            }
            // ---- hi term: 32 MMAs, no same-acc reuse inside ----
#pragma unroll
            for (int nf = 0; nf < 8; ++nf)
#pragma unroll
                for (int mf = 0; mf < 4; ++mf)
                    mma_f16(acc[mf][nf], ah[mf], bh[nf]);
            // ---- lo term ----
#pragma unroll
            for (int nf = 0; nf < 8; ++nf)
#pragma unroll
                for (int mf = 0; mf < 4; ++mf)
                    mma_f16(acc[mf][nf], ah[mf], bl[nf]);
        }
        __syncthreads();                     // done reading buf(it&1)
        ra[0] = rn[0]; ra[1] = rn[1];
    }

    // ---- bias add ----
#pragma unroll
    for (int nf = 0; nf < 8; ++nf) {
        float c0 = cbias[wid * 64 + nf * 8 + 2 * (lane & 3)];
        float c1 = cbias[wid * 64 + nf * 8 + 2 * (lane & 3) + 1];
#pragma unroll
        for (int mf = 0; mf < 4; ++mf) {
            acc[mf][nf][0] += c0; acc[mf][nf][1] += c1;
            acc[mf][nf][2] += c0; acc[mf][nf][3] += c1;
        }
    }

    if (mode) {
        // ---- per-row stats ----
#pragma unroll
        for (int mf = 0; mf < 4; ++mf) {
#pragma unroll
            for (int h = 0; h < 2; ++h) {
                float s = 0.f, q = 0.f;
#pragma unroll
                for (int nf = 0; nf < 8; ++nf) {
#pragma unroll
                    for (int jj = 0; jj < 2; ++jj) {
                        float v = acc[mf][nf][h * 2 + jj];
                        s += v; q += v * v;
                    }
                }
                s += __shfl_xor_sync(0xffffffffu, s, 1);
                s += __shfl_xor_sync(0xffffffffu, s, 2);
                q += __shfl_xor_sync(0xffffffffu, q, 1);
                q += __shfl_xor_sync(0xffffffffu, q, 2);
                if ((lane & 3) == 0) {
                    int row = mf * 16 + h * 8 + (lane >> 2);
                    redS[wid * 64 + row] = s;
                    redQ[wid * 64 + row] = q;
                }
            }
        }
        __syncthreads();
        if (tid < 64) {
            float s = 0.f, q = 0.f;
#pragma unroll
            for (int w8 = 0; w8 < 8; ++w8) { s += redS[w8 * 64 + tid]; q += redQ[w8 * 64 + tid]; }
            float mu = s * (1.f / 512.f);
            float var = q * (1.f / 512.f) - mu * mu;
            muv[tid] = mu;
            rsv[tid] = rsqrtf(var + 1e-5f);
        }
        __syncthreads();
    }

    // ---- frag store into per-warp smem tile ----
    float* tile = (float*)(sa + (size_t)wid * 16384);
#pragma unroll
    for (int mf = 0; mf < 4; ++mf) {
#pragma unroll
        for (int h = 0; h < 2; ++h) {
            int row = mf * 16 + h * 8 + (lane >> 2);
            float mu = 0.f, rs = 1.f;
            if (mode) { mu = muv[row]; rs = rsv[row]; }
#pragma unroll
            for (int nf = 0; nf < 8; ++nf) {
                int colw = nf * 8 + 2 * (lane & 3);
                float v0 = acc[mf][nf][h * 2 + 0];
                float v1 = acc[mf][nf][h * 2 + 1];
                if (mode) { v0 = (v0 - mu) * rs; v1 = (v1 - mu) * rs; }
                tile[row * 64 + colw]     = v0;
                tile[row * 64 + colw + 1] = v1;
            }
        }
    }
    __syncthreads();

    // ---- coalesced global store ----
#pragma unroll
    for (int i = 0; i < 32; ++i) {
        int idx = i * 256 + tid;
        int row = idx >> 7;
        int col = (idx & 127) * 4;
        const float* src = (const float*)(sa + (size_t)(col >> 6) * 16384) + row * 64 + (col & 63);
        float4 v = *(const float4*)src;
        size_t gi = (size_t)(m0 + row) * 512 + col;
        if (mode) {
            float4 g4 = *(const float4*)(cg + col);
            float4 b4 = *(const float4*)(cbt + col);
            float4 r4 = *(const float4*)(X + gi);
            v.x = v.x * g4.x + b4.x + r4.x;
            v.y = v.y * g4.y + b4.y + r4.y;
            v.z = v.z * g4.z + b4.z + r4.z;
            v.w = v.w * g4.w + b4.w + r4.w;
        }
        *(float4*)(outp + gi) = v;
    }
}

// =====================================================================
// pkv HMMA: partial[hw,seg] = P_h[h,:,seg] @ (KV_h + KV_l)[seg, h*64:+64]
// grid (seg=8, hw=16); block 256 thr, 8 warps: warp grid 4(M)x2(N),
// warp tile 64x32, M=256, N=64, inner 1024, BK=32.
// =====================================================================
__global__ __launch_bounds__(256)
void pkv_hmma(const float* __restrict__ Ep, const float* __restrict__ Fp)
{
    extern __shared__ char dsm[];
    const uint32_t raw = smem_u32(dsm);
    const uint32_t sb = (raw + 1023) & ~1023u;
    char* sa = dsm + (sb - raw);

    const int seg = blockIdx.x;       // 0..7
    const int hw  = blockIdx.y;       // 0..15
    const int h   = hw >> 1, w = hw & 1;
    const float* P  = w ? Fp : Ep;
    const float* KV = w ? g_V : g_K;
    const int n0base = seg * 1024;

    const int tid  = threadIdx.x;
    const int lane = tid & 31;
    const int wid  = tid >> 5;
    const int wm   = wid & 3;         // M quadrant (64 rows)
    const int wn   = wid >> 2;        // N half (32 cols)

    // stage: [A 16K][B_hi 4K][B_lo 4K] = 24K x2
    const uint32_t ST = 24576;
    const uint32_t OFF_BH = 16384, OFF_BL = 20480;

    float acc[4][4][4];
#pragma unroll
    for (int mf = 0; mf < 4; ++mf)
#pragma unroll
        for (int nf = 0; nf < 4; ++nf)
#pragma unroll
            for (int j = 0; j < 4; ++j) acc[mf][nf][j] = 0.f;

    auto ldg = [&](int c, float4* a, float4* b) {
        const int col = n0base + c * 32;
#pragma unroll
        for (int t = 0; t < 8; ++t) {
            int f = tid + t * 256;           // 2048 float4s = 256x32
            int row = f >> 3, kq = f & 7;
            a[t] = *(const float4*)(P + (size_t)(h * 256 + row) * 8192 + col + kq * 4);
        }
#pragma unroll
        for (int t = 0; t < 2; ++t) {
            int f = tid + t * 256;           // 512 float4s = 32x64
            int row = f >> 4, dq = f & 15;
            b[t] = *(const float4*)(KV + (size_t)(col + row) * 512 + h * 64 + dq * 4);
        }
    };
    auto sts = [&](int c, const float4* a, const float4* b) {
        char* dst = sa + (size_t)(c & 1) * ST;
#pragma unroll
        for (int t = 0; t < 8; ++t) {
            int f = tid + t * 256;
            int row = f >> 3, kq = f & 7;
            __half2 h0 = __floats2half2_rn(a[t].x, a[t].y);
            __half2 h1 = __floats2half2_rn(a[t].z, a[t].w);
            uint32_t off = SWZ64((uint32_t)(row * 64 + kq * 8));
            *(uint2*)(dst + off) = make_uint2(*(uint32_t*)&h0, *(uint32_t*)&h1);
        }
#pragma unroll
        for (int t = 0; t < 2; ++t) {
            int f = tid + t * 256;
            int row = f >> 4, dq = f & 15;
            float4 v = b[t];
            __half2 h0 = __floats2half2_rn(v.x, v.y);
            __half2 h1 = __floats2half2_rn(v.z, v.w);
            __half2 l0 = __floats2half2_rn(v.x - __half2float(__low2half(h0)),
                                           v.y - __half2float(__high2half(h0)));
            __half2 l1 = __floats2half2_rn(v.z - __half2float(__low2half(h1)),
                                           v.w - __half2float(__high2half(h1)));
            uint32_t off = SWZ128((uint32_t)(row * 128 + dq * 8));
            *(uint2*)(dst + OFF_BH + off) = make_uint2(*(uint32_t*)&h0, *(uint32_t*)&h1);
            *(uint2*)(dst + OFF_BL + off) = make_uint2(*(uint32_t*)&l0, *(uint32_t*)&l1);
        }
    };

    float4 ra[8], rb[2], na[8], nb[2];
    ldg(0, ra, rb);

    for (int c = 0; c < 32; ++c) {
        sts(c, ra, rb);
        if (c < 31) ldg(c + 1, na, nb);
        __syncthreads();

        const uint32_t stg = sb + (uint32_t)(c & 1) * ST;
#pragma unroll
        for (int kk = 0; kk < 2; ++kk) {
            uint32_t ah[4][4];
#pragma unroll
            for (int mf = 0; mf < 4; ++mf) {
                int m = wm * 64 + mf * 16 + (lane & 7) + ((lane >> 3) & 1) * 8;
                int ks = kk * 2 + (lane >> 4);
                ldsm_x4(ah[mf], stg + SWZ64((uint32_t)(m * 64 + ks * 16)));
            }
            // preload all B frags (x4 trans: 2 nf per ldsm)
            uint32_t bh[4][2], bl[4][2];
#pragma unroll
            for (int nfp = 0; nfp < 2; ++nfp) {
                int k = kk * 16 + (lane & 15);
                int n = wn * 32 + nfp * 16 + ((lane >> 4) & 1) * 8;
                uint32_t off = SWZ128((uint32_t)(k * 128 + n * 2));
                uint32_t r[4];
                ldsm_x4_trans(r, stg + OFF_BH + off);
                bh[nfp * 2][0] = r[0]; bh[nfp * 2][1] = r[1];
                bh[nfp * 2 + 1][0] = r[2]; bh[nfp * 2 + 1][1] = r[3];
                ldsm_x4_trans(r, stg + OFF_BL + off);
                bl[nfp * 2][0] = r[0]; bl[nfp * 2][1] = r[1];
                bl[nfp * 2 + 1][0] = r[2]; bl[nfp * 2 + 1][1] = r[3];
            }
#pragma unroll
            for (int nf = 0; nf < 4; ++nf)
#pragma unroll
                for (int mf = 0; mf < 4; ++mf)
                    mma_f16(acc[mf][nf], ah[mf], bh[nf]);
#pragma unroll
            for (int nf = 0; nf < 4; ++nf)
#pragma unroll
                for (int mf = 0; mf < 4; ++mf)
                    mma_f16(acc[mf][nf], ah[mf], bl[nf]);
        }
        __syncthreads();
#pragma unroll
        for (int t = 0; t < 8; ++t) ra[t] = na[t];
        rb[0] = nb[0]; rb[1] = nb[1];
    }

    // ---- store partials ----
    float* dst = g_part + (size_t)(hw * 8 + seg) * 16384;
#pragma unroll
    for (int mf = 0; mf < 4; ++mf) {
#pragma unroll
        for (int nf = 0; nf < 4; ++nf) {
            int m = wm * 64 + mf * 16 + (lane >> 2);
            int n = wn * 32 + nf * 8 + (lane & 3) * 2;
            *(float2*)(dst + m * 64 + n)       = make_float2(acc[mf][nf][0], acc[mf][nf][1]);
            *(float2*)(dst + (m + 8) * 64 + n) = make_float2(acc[mf][nf][2], acc[mf][nf][3]);
        }
    }
}

__global__ void pkv_reduce()
{
    int o = blockIdx.x * 256 + threadIdx.x;   // 0..262143
    int d  = o & 63;
    int k  = (o >> 6) & 255;
    int h  = (o >> 14) & 7;
    int w  = o >> 17;
    int hw = h * 2 + w;
    float s = 0.f;
#pragma unroll
    for (int sp = 0; sp < 8; sp++)
        s += g_part[(size_t)(hw * 8 + sp) * 16384 + k * 64 + d];
    float* dst = w ? g_pV : g_pK;
    dst[((h << 8) + k) * 64 + d] = s;
}

// =====================================================================
// Fused attention (fp32), 512 threads: scores -> softmax -> out
// =====================================================================
__global__ __launch_bounds__(512)
void attn_kernel()
{
    extern __shared__ float sm[];
    float* pKs = sm;                       // 256*65
    float* pVs = pKs + 256 * 65;           // 256*65
    float* Qs  = pVs + 256 * 65;           // 64*65
    float* Ss  = Qs  + 64 * 65;            // 64*257

    const int h   = blockIdx.y;
    const int n0  = blockIdx.x * 64;
    const int tid = threadIdx.x;

#pragma unroll
    for (int i = 0; i < 8; i++) {
        int f = tid + i * 512;
        int k = f >> 4, dq = f & 15;
        float4 v = *(const float4*)(g_pK + (size_t)(h * 256 + k) * 64 + dq * 4);
        float* dst = &pKs[k * 65 + dq * 4];
        dst[0] = v.x; dst[1] = v.y; dst[2] = v.z; dst[3] = v.w;
        float4 u = *(const float4*)(g_pV + (size_t)(h * 256 + k) * 64 + dq * 4);
        float* dst2 = &pVs[k * 65 + dq * 4];
        dst2[0] = u.x; dst2[1] = u.y; dst2[2] = u.z; dst2[3] = u.w;
    }
#pragma unroll
    for (int i = 0; i < 2; i++) {
        int f = tid + i * 512;
        int m = f >> 4, dq = f & 15;
        float4 v = *(const float4*)(g_Q + (size_t)(n0 + m) * 512 + h * 64 + dq * 4);
        float* dst = &Qs[m * 65 + dq * 4];
        dst[0] = v.x; dst[1] = v.y; dst[2] = v.z; dst[3] = v.w;
    }
    __syncthreads();

    const int tm = tid >> 6;   // 0..7
    const int tj = tid & 63;   // 0..63
    {
        float acc[8][4];
#pragma unroll
        for (int r = 0; r < 8; r++)
#pragma unroll
            for (int c = 0; c < 4; c++) acc[r][c] = 0.f;
#pragma unroll 4
        for (int d = 0; d < 64; d++) {
            float a[8], b[4];
#pragma unroll
            for (int r = 0; r < 8; r++) a[r] = Qs[(tm + 8 * r) * 65 + d];
#pragma unroll
            for (int c = 0; c < 4; c++) b[c] = pKs[(tj + 64 * c) * 65 + d];
#pragma unroll
            for (int r = 0; r < 8; r++)
#pragma unroll
                for (int c = 0; c < 4; c++)
                    acc[r][c] = fmaf(a[r], b[c], acc[r][c]);
        }
#pragma unroll
        for (int r = 0; r < 8; r++)
#pragma unroll
            for (int c = 0; c < 4; c++)
                Ss[(tm + 8 * r) * 257 + tj + 64 * c] = acc[r][c] * 0.125f;
    }
    __syncthreads();

    // ---- softmax: 16 warps x 4 rows ----
    {
        const int wp = tid >> 5, ln = tid & 31;
#pragma unroll
        for (int rr = 0; rr < 4; rr++) {
            int m = wp * 4 + rr;
            float v[8];
            float mx = -1e30f;
#pragma unroll
            for (int i = 0; i < 8; i++) { v[i] = Ss[m * 257 + ln + 32 * i]; mx = fmaxf(mx, v[i]); }
#pragma unroll
            for (int o = 16; o > 0; o >>= 1) mx = fmaxf(mx, __shfl_xor_sync(0xffffffffu, mx, o));
            float sum = 0.f;
#pragma unroll
            for (int i = 0; i < 8; i++) { v[i] = __expf(v[i] - mx); sum += v[i]; }
#pragma unroll
            for (int o = 16; o > 0; o >>= 1) sum += __shfl_xor_sync(0xffffffffu, sum, o);
            float inv = 1.f / sum;
#pragma unroll
            for (int i = 0; i < 8; i++) Ss[m * 257 + ln + 32 * i] = v[i] * inv;
        }
    }
    __syncthreads();

    // ---- out: O[m, d] = sum_j attn[m,j] * pV[j,d] ----
    {
        float o2[8];
#pragma unroll
        for (int r = 0; r < 8; r++) o2[r] = 0.f;
#pragma unroll 4
        for (int j = 0; j < 256; j++) {
            float b0 = pVs[j * 65 + tj];
#pragma unroll
            for (int r = 0; r < 8; r++)
                o2[r] = fmaf(Ss[(tm + 8 * r) * 257 + j], b0, o2[r]);
        }
#pragma unroll
        for (int r = 0; r < 8; r++)
            g_x[(size_t)(n0 + tm + 8 * r) * 512 + h * 64 + tj] = o2[r];
    }
}

// =====================================================================
// node LayerNorm + residual
// =====================================================================
__global__ __launch_bounds__(128)
void node_ln_kernel(const float* __restrict__ nf,
                    const float* __restrict__ gam, const float* __restrict__ bet,
                    float* __restrict__ out)
{
    const int row = blockIdx.x;
    const int tid = threadIdx.x;
    const float* xr = g_x + (size_t)row * 512;

    float v[4];
    float s = 0.f, q = 0.f;
#pragma unroll
    for (int i = 0; i < 4; i++) {
        v[i] = xr[tid + 128 * i];
        s += v[i];
        q += v[i] * v[i];
    }
#pragma unroll
    for (int o = 16; o > 0; o >>= 1) {
        s += __shfl_xor_sync(0xffffffffu, s, o);
        q += __shfl_xor_sync(0xffffffffu, q, o);
    }
    __shared__ float rs[4], rq[4], mv[2];
    const int wp = tid >> 5, ln = tid & 31;
    if (ln == 0) { rs[wp] = s; rq[wp] = q; }
    __syncthreads();
    if (tid == 0) {
        float S = rs[0] + rs[1] + rs[2] + rs[3];
        float Qq = rq[0] + rq[1] + rq[2] + rq[3];
        float mu  = S * (1.f / 512.f);
        float var = Qq * (1.f / 512.f) - mu * mu;
        mv[0] = mu;
        mv[1] = rsqrtf(var + 1e-5f);
    }
    __syncthreads();
    const float mu = mv[0], rstd = mv[1];
#pragma unroll
    for (int i = 0; i < 4; i++) {
        int c = tid + 128 * i;
        out[(size_t)row * 512 + c] =
            (v[i] - mu) * rstd * gam[c] + bet[c] + nf[(size_t)row * 512 + c];
    }
}

// =====================================================================
// launch
// =====================================================================
extern "C" void kernel_launch(void* const* d_in, const int* in_sizes, int n_in,
                              void* d_out, int out_size)
{
    const float* node  = (const float*)d_in[0];
    const float* edge  = (const float*)d_in[1];
    const float* Wq    = (const float*)d_in[2];
    const float* bq    = (const float*)d_in[3];
    const float* Wk    = (const float*)d_in[4];
    const float* bk    = (const float*)d_in[5];
    const float* Wv    = (const float*)d_in[6];
    const float* bv    = (const float*)d_in[7];
    const float* We    = (const float*)d_in[8];
    const float* be    = (const float*)d_in[9];
    const float* Ep    = (const float*)d_in[10];
    const float* Fp    = (const float*)d_in[11];
    const float* ln_ng = (const float*)d_in[12];
    const float* ln_nb = (const float*)d_in[13];
    const float* ln_eg = (const float*)d_in[14];
    const float* ln_eb = (const float*)d_in[15];
    float* out = (float*)d_out;

    const int attn_smem = (2 * 256 * 65 + 64 * 65 + 64 * 257) * 4;  // 215,552 B
    cudaFuncSetAttribute(attn_kernel, cudaFuncAttributeMaxDynamicSharedMemorySize, attn_smem);
    const int gemm_smem = 150016 + 1024;
    cudaFuncSetAttribute(hmma_gemm, cudaFuncAttributeMaxDynamicSharedMemorySize, gemm_smem);
    const int pkv_smem = 49152 + 1024;
    cudaFuncSetAttribute(pkv_hmma, cudaFuncAttributeMaxDynamicSharedMemorySize, pkv_smem);

    // 0) W -> fp16 hi/lo
    convert_w<<<4096, 256>>>(Wq, Wk, Wv, We);
    // 1) QKV projections
    hmma_gemm<<<dim3(128, 3), 256, gemm_smem>>>(node, 0, 0, bq, bk, bv,
                                                nullptr, nullptr, nullptr);
    // 2) low-rank K/V projections (HMMA split-inner + reduce)
    pkv_hmma<<<dim3(8, 16), 256, pkv_smem>>>(Ep, Fp);
    pkv_reduce<<<1024, 256>>>();
    // 3) fused attention -> g_x
    attn_kernel<<<dim3(128, 8), 512, attn_smem>>>();
    // 4) node LN + residual -> out[0 : N*C)
    node_ln_kernel<<<8192, 128>>>(node, ln_ng, ln_nb, out);
    // 5) edge GEMM + bias + LN + residual -> out[N*C : )
    hmma_gemm<<<dim3(2048, 1), 256, gemm_smem>>>(edge, 3, 1, be, be, be,
                                                 ln_eg, ln_eb, out + (size_t)NN * CC);
}

// round 14
// speedup vs baseline: 1.4205x; 1.4179x over previous
#include <cuda_runtime.h>
#include <cuda_fp16.h>
#include <cstdint>

#define NN 8192
#define EN 131072
#define CC 512
#define HH 8
#define DD 64
#define KR 256

// ---------------- scratch (__device__ globals, no allocation) ----------------
__device__ float g_Q[NN * CC];
__device__ float g_K[NN * CC];
__device__ float g_V[NN * CC];
__device__ float g_part[512 * 4096];     // 2M floats: pkv partials (128 x 16384)
__device__ float g_pK[HH * KR * DD];
__device__ float g_pV[HH * KR * DD];
__device__ float g_x[NN * CC];
__device__ __half g_Wh[4 * 512 * 512];

// ===================== helpers =====================
__device__ __forceinline__ uint32_t smem_u32(const void* p) {
    uint32_t a;
    asm("{ .reg .u64 t; cvta.to.shared.u64 t, %1; cvt.u32.u64 %0, t; }" : "=r"(a) : "l"(p));
    return a;
}
#define SWZ64(b)  ((b) ^ (((b) >> 3) & 0x30))
#define SWZ128(b) ((b) ^ (((b) >> 3) & 0x70))

__device__ __forceinline__ void ldsm_x4(uint32_t* r, uint32_t a) {
    asm volatile("ldmatrix.sync.aligned.m8n8.x4.shared.b16 {%0,%1,%2,%3}, [%4];"
                 : "=r"(r[0]), "=r"(r[1]), "=r"(r[2]), "=r"(r[3]) : "r"(a));
}
__device__ __forceinline__ void ldsm_x4_trans(uint32_t* r, uint32_t a) {
    asm volatile("ldmatrix.sync.aligned.m8n8.x4.trans.shared.b16 {%0,%1,%2,%3}, [%4];"
                 : "=r"(r[0]), "=r"(r[1]), "=r"(r[2]), "=r"(r[3]) : "r"(a));
}
__device__ __forceinline__ void mma_f16(float* d, const uint32_t* a, const uint32_t* b) {
    asm volatile("mma.sync.aligned.m16n8k16.row.col.f32.f16.f16.f32 "
                 "{%0,%1,%2,%3}, {%4,%5,%6,%7}, {%8,%9}, {%0,%1,%2,%3};"
                 : "+f"(d[0]), "+f"(d[1]), "+f"(d[2]), "+f"(d[3])
                 : "r"(a[0]), "r"(a[1]), "r"(a[2]), "r"(a[3]), "r"(b[0]), "r"(b[1]));
}
__device__ __forceinline__ void cp_async16(uint32_t s, const void* g) {
    asm volatile("cp.async.cg.shared.global [%0], [%1], 16;" :: "r"(s), "l"(g) : "memory");
}
__device__ __forceinline__ void cp_commit() {
    asm volatile("cp.async.commit_group;" ::: "memory");
}
template<int N> __device__ __forceinline__ void cp_wait() {
    asm volatile("cp.async.wait_group %0;" :: "n"(N) : "memory");
}

// =====================================================================
// W -> fp16 pre-conversion (4 weight matrices, 512x512 each; hi only —
// the A-side residual term carries the split-precision correction)
// =====================================================================
__global__ void convert_w(const float* __restrict__ Wq, const float* __restrict__ Wk,
                          const float* __restrict__ Wv, const float* __restrict__ We)
{
    int i = blockIdx.x * 256 + threadIdx.x;
    int w = i >> 18;
    int off = i & 262143;
    const float* src = (w == 0) ? Wq : (w == 1) ? Wk : (w == 2) ? Wv : We;
    g_Wh[i] = __float2half_rn(src[off]);
}

// =====================================================================
// HMMA fp16 GEMM: D[M,512] = X_h[M,512] @ W_h^T + bias
// (A hi-only x W hi-only; error ~3e-4 per calibrated model)
// mode 0: out = g_Q/g_K/g_V (blockIdx.y), bias only
// mode 1: out = out_edge, fused LayerNorm + residual(X)
// Block 64x512, BK=32, 8 warps (warp tile 64x64), double-buffered smem.
// Epilogue: direct float2 frag stores (32B-sector aligned per lane quad).
// =====================================================================
__global__ __launch_bounds__(256)
void hmma_gemm(const float* __restrict__ X, int wbase, int mode,
               const float* __restrict__ b0, const float* __restrict__ b1,
               const float* __restrict__ b2,
               const float* __restrict__ gam, const float* __restrict__ bet,
               float* __restrict__ out_edge)
{
    extern __shared__ char dsm[];
    const uint32_t raw = smem_u32(dsm);
    const uint32_t sb = (raw + 1023) & ~1023u;
    char* sa = dsm + (sb - raw);

    const int tid  = threadIdx.x;
    const int lane = tid & 31;
    const int wid  = tid >> 5;
    const int y    = blockIdx.y;
    const int m0   = blockIdx.x * 64;

    const float* bias = (y == 0) ? b0 : (y == 1) ? b1 : b2;
    const int w = wbase + y;
    float* outp = mode ? out_edge : ((y == 0) ? g_Q : (y == 1) ? g_K : g_V);
    const __half* WH = g_Wh + ((size_t)w << 18);

    // stage: [A 4K][B 32K] = 36K, x2
    const uint32_t ST = 36864;
    const uint32_t OFF_BH = 4096;
    const uint32_t OFF_RED = 73728;
    float* redS  = (float*)(sa + OFF_RED);   // 8*64
    float* redQ  = redS + 512;
    float* muv   = redQ + 512;               // 64
    float* rsv   = muv + 64;                 // 64
    float* cbias = rsv + 64;                 // 512
    float* cg    = cbias + 512;              // 512
    float* cbt   = cg + 512;                 // 512

    for (int i = tid; i < 512; i += 256) {
        cbias[i] = bias[i];
        if (mode) { cg[i] = gam[i]; cbt[i] = bet[i]; }
    }

    float acc[4][8][4];
#pragma unroll
    for (int mf = 0; mf < 4; ++mf)
#pragma unroll
        for (int nf = 0; nf < 8; ++nf)
#pragma unroll
            for (int j = 0; j < 4; ++j) acc[mf][nf][j] = 0.f;

    // ---------- loaders ----------
    auto ldgA = [&](int it, float4* r) {
        const int k0 = it * 32;
#pragma unroll
        for (int h = 0; h < 2; ++h) {
            int i = tid + h * 256;           // float4 index, 512 total
            int row = i >> 3, kq = i & 7;
            r[h] = *(const float4*)(X + (size_t)(m0 + row) * 512 + k0 + kq * 4);
        }
    };
    auto stsA = [&](int it, const float4* r) {
        char* dst = sa + (size_t)(it & 1) * ST;
#pragma unroll
        for (int h = 0; h < 2; ++h) {
            int i = tid + h * 256;
            int row = i >> 3, kq = i & 7;
            __half2 h0 = __floats2half2_rn(r[h].x, r[h].y);
            __half2 h1 = __floats2half2_rn(r[h].z, r[h].w);
            uint32_t off = SWZ64((uint32_t)(row * 64 + kq * 8));
            *(uint2*)(dst + off) = make_uint2(*(uint32_t*)&h0, *(uint32_t*)&h1);
        }
    };
    auto loadB = [&](int it) {
        const int k0 = it * 32;
        const uint32_t dH = sb + (uint32_t)(it & 1) * ST + OFF_BH;
#pragma unroll
        for (int h = 0; h < 8; ++h) {
            int c = tid + h * 256;           // 0..2047 16B chunks (512 rows x 4)
            int n = c >> 2, sub = c & 3;
            uint32_t off = SWZ64((uint32_t)(n * 64 + sub * 16));
            cp_async16(dH + off, WH + (size_t)n * 512 + k0 + sub * 8);
        }
        cp_commit();
    };

    float4 ra[2], rn[2];
    ldgA(0, ra);
    loadB(0);

    for (int it = 0; it < 16; ++it) {
        stsA(it, ra);                        // write buf(it&1)
        if (it < 15) {
            ldgA(it + 1, rn);                // LDGs fly during compute
            loadB(it + 1);
        }
        if (it < 15) cp_wait<1>(); else cp_wait<0>();
        __syncthreads();                     // stage it visible

        const uint32_t stg = sb + (uint32_t)(it & 1) * ST;
#pragma unroll
        for (int kk = 0; kk < 2; ++kk) {
            // ---- preload A frags ----
            uint32_t ah[4][4];
#pragma unroll
            for (int mf = 0; mf < 4; ++mf) {
                int m = mf * 16 + (lane & 7) + ((lane >> 3) & 1) * 8;
                int ks = kk * 2 + (lane >> 4);
                ldsm_x4(ah[mf], stg + SWZ64((uint32_t)(m * 64 + ks * 16)));
            }
            // ---- preload all B frags via x4 (2 nf per ldsm) ----
            uint32_t bh[8][2];
#pragma unroll
            for (int nfp = 0; nfp < 4; ++nfp) {
                int n  = wid * 64 + nfp * 16 + ((lane >> 4) & 1) * 8 + (lane & 7);
                int ks = kk * 2 + ((lane >> 3) & 1);
                uint32_t off = SWZ64((uint32_t)(n * 64 + ks * 16));
                uint32_t r[4];
                ldsm_x4(r, stg + OFF_BH + off);
                bh[nfp * 2][0] = r[0]; bh[nfp * 2][1] = r[1];
                bh[nfp * 2 + 1][0] = r[2]; bh[nfp * 2 + 1][1] = r[3];
            }
#pragma unroll
            for (int nf = 0; nf < 8; ++nf)
#pragma unroll
                for (int mf = 0; mf < 4; ++mf)
                    mma_f16(acc[mf][nf], ah[mf], bh[nf]);
        }
        __syncthreads();                     // done reading buf(it&1)
        ra[0] = rn[0]; ra[1] = rn[1];
    }

    // ---- bias add ----
#pragma unroll
    for (int nf = 0; nf < 8; ++nf) {
        float c0 = cbias[wid * 64 + nf * 8 + 2 * (lane & 3)];
        float c1 = cbias[wid * 64 + nf * 8 + 2 * (lane & 3) + 1];
#pragma unroll
        for (int mf = 0; mf < 4; ++mf) {
            acc[mf][nf][0] += c0; acc[mf][nf][1] += c1;
            acc[mf][nf][2] += c0; acc[mf][nf][3] += c1;
        }
    }

    if (mode) {
        // ---- per-row stats ----
#pragma unroll
        for (int mf = 0; mf < 4; ++mf) {
#pragma unroll
            for (int h = 0; h < 2; ++h) {
                float s = 0.f, q = 0.f;
#pragma unroll
                for (int nf = 0; nf < 8; ++nf) {
#pragma unroll
                    for (int jj = 0; jj < 2; ++jj) {
                        float v = acc[mf][nf][h * 2 + jj];
                        s += v; q += v * v;
                    }
                }
                s += __shfl_xor_sync(0xffffffffu, s, 1);
                s += __shfl_xor_sync(0xffffffffu, s, 2);
                q += __shfl_xor_sync(0xffffffffu, q, 1);
                q += __shfl_xor_sync(0xffffffffu, q, 2);
                if ((lane & 3) == 0) {
                    int row = mf * 16 + h * 8 + (lane >> 2);
                    redS[wid * 64 + row] = s;
                    redQ[wid * 64 + row] = q;
                }
            }
        }
        __syncthreads();
        if (tid < 64) {
            float s = 0.f, q = 0.f;
#pragma unroll
            for (int w8 = 0; w8 < 8; ++w8) { s += redS[w8 * 64 + tid]; q += redQ[w8 * 64 + tid]; }
            float mu = s * (1.f / 512.f);
            float var = q * (1.f / 512.f) - mu * mu;
            muv[tid] = mu;
            rsv[tid] = rsqrtf(var + 1e-5f);
        }
        __syncthreads();
    }

    // ---- direct global store from frags (32B-sector aligned per quad) ----
#pragma unroll
    for (int mf = 0; mf < 4; ++mf) {
#pragma unroll
        for (int h = 0; h < 2; ++h) {
            int row = mf * 16 + h * 8 + (lane >> 2);
            float mu = 0.f, rs = 1.f;
            if (mode) { mu = muv[row]; rs = rsv[row]; }
#pragma unroll
            for (int nf = 0; nf < 8; ++nf) {
                int col = wid * 64 + nf * 8 + 2 * (lane & 3);
                float v0 = acc[mf][nf][h * 2 + 0];
                float v1 = acc[mf][nf][h * 2 + 1];
                size_t gi = (size_t)(m0 + row) * 512 + col;
                if (mode) {
                    v0 = (v0 - mu) * rs * cg[col]     + cbt[col];
                    v1 = (v1 - mu) * rs * cg[col + 1] + cbt[col + 1];
                    float2 r2 = *(const float2*)(X + gi);
                    v0 += r2.x; v1 += r2.y;
                }
                *(float2*)(outp + gi) = make_float2(v0, v1);
            }
        }
    }
}

// =====================================================================
// pkv HMMA: partial[hw,seg] = P_h[h,:,seg] @ (KV_h + KV_l)[seg, h*64:+64]
// grid (seg=8, hw=16); block 256 thr, 8 warps: warp grid 4(M)x2(N),
// warp tile 64x32, M=256, N=64, inner 1024, BK=32.  (2-term KV kept.)
// =====================================================================
__global__ __launch_bounds__(256)
void pkv_hmma(const float* __restrict__ Ep, const float* __restrict__ Fp)
{
    extern __shared__ char dsm[];
    const uint32_t raw = smem_u32(dsm);
    const uint32_t sb = (raw + 1023) & ~1023u;
    char* sa = dsm + (sb - raw);

    const int seg = blockIdx.x;       // 0..7
    const int hw  = blockIdx.y;       // 0..15
    const int h   = hw >> 1, w = hw & 1;
    const float* P  = w ? Fp : Ep;
    const float* KV = w ? g_V : g_K;
    const int n0base = seg * 1024;

    const int tid  = threadIdx.x;
    const int lane = tid & 31;
    const int wid  = tid >> 5;
    const int wm   = wid & 3;         // M quadrant (64 rows)
    const int wn   = wid >> 2;        // N half (32 cols)

    // stage: [A 16K][B_hi 4K][B_lo 4K] = 24K x2
    const uint32_t ST = 24576;
    const uint32_t OFF_BH = 16384, OFF_BL = 20480;

    float acc[4][4][4];
#pragma unroll
    for (int mf = 0; mf < 4; ++mf)
#pragma unroll
        for (int nf = 0; nf < 4; ++nf)
#pragma unroll
            for (int j = 0; j < 4; ++j) acc[mf][nf][j] = 0.f;

    auto ldg = [&](int c, float4* a, float4* b) {
        const int col = n0base + c * 32;
#pragma unroll
        for (int t = 0; t < 8; ++t) {
            int f = tid + t * 256;           // 2048 float4s = 256x32
            int row = f >> 3, kq = f & 7;
            a[t] = *(const float4*)(P + (size_t)(h * 256 + row) * 8192 + col + kq * 4);
        }
#pragma unroll
        for (int t = 0; t < 2; ++t) {
            int f = tid + t * 256;           // 512 float4s = 32x64
            int row = f >> 4, dq = f & 15;
            b[t] = *(const float4*)(KV + (size_t)(col + row) * 512 + h * 64 + dq * 4);
        }
    };
    auto sts = [&](int c, const float4* a, const float4* b) {
        char* dst = sa + (size_t)(c & 1) * ST;
#pragma unroll
        for (int t = 0; t < 8; ++t) {
            int f = tid + t * 256;
            int row = f >> 3, kq = f & 7;
            __half2 h0 = __floats2half2_rn(a[t].x, a[t].y);
            __half2 h1 = __floats2half2_rn(a[t].z, a[t].w);
            uint32_t off = SWZ64((uint32_t)(row * 64 + kq * 8));
            *(uint2*)(dst + off) = make_uint2(*(uint32_t*)&h0, *(uint32_t*)&h1);
        }
#pragma unroll
        for (int t = 0; t < 2; ++t) {
            int f = tid + t * 256;
            int row = f >> 4, dq = f & 15;
            float4 v = b[t];
            __half2 h0 = __floats2half2_rn(v.x, v.y);
            __half2 h1 = __floats2half2_rn(v.z, v.w);
            __half2 l0 = __floats2half2_rn(v.x - __half2float(__low2half(h0)),
                                           v.y - __half2float(__high2half(h0)));
            __half2 l1 = __floats2half2_rn(v.z - __half2float(__low2half(h1)),
                                           v.w - __half2float(__high2half(h1)));
            uint32_t off = SWZ128((uint32_t)(row * 128 + dq * 8));
            *(uint2*)(dst + OFF_BH + off) = make_uint2(*(uint32_t*)&h0, *(uint32_t*)&h1);
            *(uint2*)(dst + OFF_BL + off) = make_uint2(*(uint32_t*)&l0, *(uint32_t*)&l1);
        }
    };

    float4 ra[8], rb[2], na[8], nb[2];
    ldg(0, ra, rb);

    for (int c = 0; c < 32; ++c) {
        sts(c, ra, rb);
        if (c < 31) ldg(c + 1, na, nb);
        __syncthreads();

        const uint32_t stg = sb + (uint32_t)(c & 1) * ST;
#pragma unroll
        for (int kk = 0; kk < 2; ++kk) {
            uint32_t ah[4][4];
#pragma unroll
            for (int mf = 0; mf < 4; ++mf) {
                int m = wm * 64 + mf * 16 + (lane & 7) + ((lane >> 3) & 1) * 8;
                int ks = kk * 2 + (lane >> 4);
                ldsm_x4(ah[mf], stg + SWZ64((uint32_t)(m * 64 + ks * 16)));
            }
            // preload all B frags (x4 trans: 2 nf per ldsm)
            uint32_t bh[4][2], bl[4][2];
#pragma unroll
            for (int nfp = 0; nfp < 2; ++nfp) {
                int k = kk * 16 + (lane & 15);
                int n = wn * 32 + nfp * 16 + ((lane >> 4) & 1) * 8;
                uint32_t off = SWZ128((uint32_t)(k * 128 + n * 2));
                uint32_t r[4];
                ldsm_x4_trans(r, stg + OFF_BH + off);
                bh[nfp * 2][0] = r[0]; bh[nfp * 2][1] = r[1];
                bh[nfp * 2 + 1][0] = r[2]; bh[nfp * 2 + 1][1] = r[3];
                ldsm_x4_trans(r, stg + OFF_BL + off);
                bl[nfp * 2][0] = r[0]; bl[nfp * 2][1] = r[1];
                bl[nfp * 2 + 1][0] = r[2]; bl[nfp * 2 + 1][1] = r[3];
            }
#pragma unroll
            for (int nf = 0; nf < 4; ++nf)
#pragma unroll
                for (int mf = 0; mf < 4; ++mf)
                    mma_f16(acc[mf][nf], ah[mf], bh[nf]);
#pragma unroll
            for (int nf = 0; nf < 4; ++nf)
#pragma unroll
                for (int mf = 0; mf < 4; ++mf)
                    mma_f16(acc[mf][nf], ah[mf], bl[nf]);
        }
        __syncthreads();
#pragma unroll
        for (int t = 0; t < 8; ++t) ra[t] = na[t];
        rb[0] = nb[0]; rb[1] = nb[1];
    }

    // ---- store partials ----
    float* dst = g_part + (size_t)(hw * 8 + seg) * 16384;
#pragma unroll
    for (int mf = 0; mf < 4; ++mf) {
#pragma unroll
        for (int nf = 0; nf < 4; ++nf) {
            int m = wm * 64 + mf * 16 + (lane >> 2);
            int n = wn * 32 + nf * 8 + (lane & 3) * 2;
            *(float2*)(dst + m * 64 + n)       = make_float2(acc[mf][nf][0], acc[mf][nf][1]);
            *(float2*)(dst + (m + 8) * 64 + n) = make_float2(acc[mf][nf][2], acc[mf][nf][3]);
        }
    }
}

__global__ void pkv_reduce()
{
    int o = blockIdx.x * 256 + threadIdx.x;   // 0..262143
    int d  = o & 63;
    int k  = (o >> 6) & 255;
    int h  = (o >> 14) & 7;
    int w  = o >> 17;
    int hw = h * 2 + w;
    float s = 0.f;
#pragma unroll
    for (int sp = 0; sp < 8; sp++)
        s += g_part[(size_t)(hw * 8 + sp) * 16384 + k * 64 + d];
    float* dst = w ? g_pV : g_pK;
    dst[((h << 8) + k) * 64 + d] = s;
}

// =====================================================================
// Fused attention (fp32), 512 threads: scores -> softmax -> out
// =====================================================================
__global__ __launch_bounds__(512)
void attn_kernel()
{
    extern __shared__ float sm[];
    float* pKs = sm;                       // 256*65
    float* pVs = pKs + 256 * 65;           // 256*65
    float* Qs  = pVs + 256 * 65;           // 64*65
    float* Ss  = Qs  + 64 * 65;            // 64*257

    const int h   = blockIdx.y;
    const int n0  = blockIdx.x * 64;
    const int tid = threadIdx.x;

#pragma unroll
    for (int i = 0; i < 8; i++) {
        int f = tid + i * 512;
        int k = f >> 4, dq = f & 15;
        float4 v = *(const float4*)(g_pK + (size_t)(h * 256 + k) * 64 + dq * 4);
        float* dst = &pKs[k * 65 + dq * 4];
        dst[0] = v.x; dst[1] = v.y; dst[2] = v.z; dst[3] = v.w;
        float4 u = *(const float4*)(g_pV + (size_t)(h * 256 + k) * 64 + dq * 4);
        float* dst2 = &pVs[k * 65 + dq * 4];
        dst2[0] = u.x; dst2[1] = u.y; dst2[2] = u.z; dst2[3] = u.w;
    }
#pragma unroll
    for (int i = 0; i < 2; i++) {
        int f = tid + i * 512;
        int m = f >> 4, dq = f & 15;
        float4 v = *(const float4*)(g_Q + (size_t)(n0 + m) * 512 + h * 64 + dq * 4);
        float* dst = &Qs[m * 65 + dq * 4];
        dst[0] = v.x; dst[1] = v.y; dst[2] = v.z; dst[3] = v.w;
    }
    __syncthreads();

    const int tm = tid >> 6;   // 0..7
    const int tj = tid & 63;   // 0..63
    {
        float acc[8][4];
#pragma unroll
        for (int r = 0; r < 8; r++)
#pragma unroll
            for (int c = 0; c < 4; c++) acc[r][c] = 0.f;
#pragma unroll 4
        for (int d = 0; d < 64; d++) {
            float a[8], b[4];
#pragma unroll
            for (int r = 0; r < 8; r++) a[r] = Qs[(tm + 8 * r) * 65 + d];
#pragma unroll
            for (int c = 0; c < 4; c++) b[c] = pKs[(tj + 64 * c) * 65 + d];
#pragma unroll
            for (int r = 0; r < 8; r++)
#pragma unroll
                for (int c = 0; c < 4; c++)
                    acc[r][c] = fmaf(a[r], b[c], acc[r][c]);
        }
#pragma unroll
        for (int r = 0; r < 8; r++)
#pragma unroll
            for (int c = 0; c < 4; c++)
                Ss[(tm + 8 * r) * 257 + tj + 64 * c] = acc[r][c] * 0.125f;
    }
    __syncthreads();

    // ---- softmax: 16 warps x 4 rows ----
    {
        const int wp = tid >> 5, ln = tid & 31;
#pragma unroll
        for (int rr = 0; rr < 4; rr++) {
            int m = wp * 4 + rr;
            float v[8];
            float mx = -1e30f;
#pragma unroll
            for (int i = 0; i < 8; i++) { v[i] = Ss[m * 257 + ln + 32 * i]; mx = fmaxf(mx, v[i]); }
#pragma unroll
            for (int o = 16; o > 0; o >>= 1) mx = fmaxf(mx, __shfl_xor_sync(0xffffffffu, mx, o));
            float sum = 0.f;
#pragma unroll
            for (int i = 0; i < 8; i++) { v[i] = __expf(v[i] - mx); sum += v[i]; }
#pragma unroll
            for (int o = 16; o > 0; o >>= 1) sum += __shfl_xor_sync(0xffffffffu, sum, o);
            float inv = 1.f / sum;
#pragma unroll
            for (int i = 0; i < 8; i++) Ss[m * 257 + ln + 32 * i] = v[i] * inv;
        }
    }
    __syncthreads();

    // ---- out: O[m, d] = sum_j attn[m,j] * pV[j,d] ----
    {
        float o2[8];
#pragma unroll
        for (int r = 0; r < 8; r++) o2[r] = 0.f;
#pragma unroll 4
        for (int j = 0; j < 256; j++) {
            float b0 = pVs[j * 65 + tj];
#pragma unroll
            for (int r = 0; r < 8; r++)
                o2[r] = fmaf(Ss[(tm + 8 * r) * 257 + j], b0, o2[r]);
        }
#pragma unroll
        for (int r = 0; r < 8; r++)
            g_x[(size_t)(n0 + tm + 8 * r) * 512 + h * 64 + tj] = o2[r];
    }
}

// =====================================================================
// node LayerNorm + residual
// =====================================================================
__global__ __launch_bounds__(128)
void node_ln_kernel(const float* __restrict__ nf,
                    const float* __restrict__ gam, const float* __restrict__ bet,
                    float* __restrict__ out)
{
    const int row = blockIdx.x;
    const int tid = threadIdx.x;
    const float* xr = g_x + (size_t)row * 512;

    float v[4];
    float s = 0.f, q = 0.f;
#pragma unroll
    for (int i = 0; i < 4; i++) {
        v[i] = xr[tid + 128 * i];
        s += v[i];
        q += v[i] * v[i];
    }
#pragma unroll
    for (int o = 16; o > 0; o >>= 1) {
        s += __shfl_xor_sync(0xffffffffu, s, o);
        q += __shfl_xor_sync(0xffffffffu, q, o);
    }
    __shared__ float rs[4], rq[4], mv[2];
    const int wp = tid >> 5, ln = tid & 31;
    if (ln == 0) { rs[wp] = s; rq[wp] = q; }
    __syncthreads();
    if (tid == 0) {
        float S = rs[0] + rs[1] + rs[2] + rs[3];
        float Qq = rq[0] + rq[1] + rq[2] + rq[3];
        float mu  = S * (1.f / 512.f);
        float var = Qq * (1.f / 512.f) - mu * mu;
        mv[0] = mu;
        mv[1] = rsqrtf(var + 1e-5f);
    }
    __syncthreads();
    const float mu = mv[0], rstd = mv[1];
#pragma unroll
    for (int i = 0; i < 4; i++) {
        int c = tid + 128 * i;
        out[(size_t)row * 512 + c] =
            (v[i] - mu) * rstd * gam[c] + bet[c] + nf[(size_t)row * 512 + c];
    }
}

// =====================================================================
// launch
// =====================================================================
extern "C" void kernel_launch(void* const* d_in, const int* in_sizes, int n_in,
                              void* d_out, int out_size)
{
    const float* node  = (const float*)d_in[0];
    const float* edge  = (const float*)d_in[1];
    const float* Wq    = (const float*)d_in[2];
    const float* bq    = (const float*)d_in[3];
    const float* Wk    = (const float*)d_in[4];
    const float* bk    = (const float*)d_in[5];
    const float* Wv    = (const float*)d_in[6];
    const float* bv    = (const float*)d_in[7];
    const float* We    = (const float*)d_in[8];
    const float* be    = (const float*)d_in[9];
    const float* Ep    = (const float*)d_in[10];
    const float* Fp    = (const float*)d_in[11];
    const float* ln_ng = (const float*)d_in[12];
    const float* ln_nb = (const float*)d_in[13];
    const float* ln_eg = (const float*)d_in[14];
    const float* ln_eb = (const float*)d_in[15];
    float* out = (float*)d_out;

    const int attn_smem = (2 * 256 * 65 + 64 * 65 + 64 * 257) * 4;  // 215,552 B
    cudaFuncSetAttribute(attn_kernel, cudaFuncAttributeMaxDynamicSharedMemorySize, attn_smem);
    const int gemm_smem = 73728 + 10752 + 1024;   // stages + epilogue arrays + align pad
    cudaFuncSetAttribute(hmma_gemm, cudaFuncAttributeMaxDynamicSharedMemorySize, gemm_smem);
    const int pkv_smem = 49152 + 1024;
    cudaFuncSetAttribute(pkv_hmma, cudaFuncAttributeMaxDynamicSharedMemorySize, pkv_smem);

    // 0) W -> fp16
    convert_w<<<4096, 256>>>(Wq, Wk, Wv, We);
    // 1) QKV projections
    hmma_gemm<<<dim3(128, 3), 256, gemm_smem>>>(node, 0, 0, bq, bk, bv,
                                                nullptr, nullptr, nullptr);
    // 2) low-rank K/V projections (HMMA split-inner + reduce)
    pkv_hmma<<<dim3(8, 16), 256, pkv_smem>>>(Ep, Fp);
    pkv_reduce<<<1024, 256>>>();
    // 3) fused attention -> g_x
    attn_kernel<<<dim3(128, 8), 512, attn_smem>>>();
    // 4) node LN + residual -> out[0 : N*C)
    node_ln_kernel<<<8192, 128>>>(node, ln_ng, ln_nb, out);
    // 5) edge GEMM + bias + LN + residual -> out[N*C : )
    hmma_gemm<<<dim3(2048, 1), 256, gemm_smem>>>(edge, 3, 1, be, be, be,
                                                 ln_eg, ln_eb, out + (size_t)NN * CC);
}